// round 5
// baseline (speedup 1.0000x reference)
#include <cuda_runtime.h>
#include <cuda_bf16.h>

#define NTOK 8192
#define CIN 512
#define DKH 64
#define BM 32
#define BN 16
#define PCOLS 640

// Scratch for projected Q/K/V (static device memory; no runtime allocation).
__device__ float g_q[2][NTOK * DKH];   // 2 x 2 MB
__device__ float g_k[2][NTOK * DKH];   // 2 x 2 MB
__device__ float g_v[2][NTOK * CIN];   // 2 x 16 MB

// ---------------------------------------------------------------------------
// Kernel 1: fused QKV projection. C = A[16384? no: per-image 8192,512] @ B[512,640]
// where B columns [0,64)=Wq, [64,128)=Wk, [128,640)=Wv. 64x64 output tiles.
// ---------------------------------------------------------------------------
__global__ __launch_bounds__(256, 2)
void proj_kernel(const float* __restrict__ im1, const float* __restrict__ im2,
                 const float* __restrict__ Wq, const float* __restrict__ Wk,
                 const float* __restrict__ Wv) {
    const int img = blockIdx.z;
    const float* __restrict__ A = img ? im2 : im1;
    float* __restrict__ q = g_q[img];
    float* __restrict__ k = g_k[img];
    float* __restrict__ v = g_v[img];

    __shared__ float As[64][17];
    __shared__ float Bs[16][65];

    const int tid = threadIdx.x;
    const int tx = tid & 15;
    const int ty = tid >> 4;
    const int rowBase = blockIdx.x * 64;
    const int colBase = blockIdx.y * 64;

    float acc[4][4] = {};

    for (int kt = 0; kt < CIN; kt += 16) {
        {   // A tile: 64 rows x 16 k, float4 per thread
            int r  = tid >> 2;
            int kk = (tid & 3) << 2;
            float4 a4 = *(const float4*)(A + (size_t)(rowBase + r) * CIN + kt + kk);
            As[r][kk] = a4.x; As[r][kk + 1] = a4.y; As[r][kk + 2] = a4.z; As[r][kk + 3] = a4.w;
        }
        {   // B tile: 16 k x 64 cols (branch is uniform per block)
            int kk   = tid >> 4;
            int c0   = (tid & 15) << 2;
            int kidx = kt + kk;
            #pragma unroll
            for (int j = 0; j < 4; j++) {
                int c = colBase + c0 + j;
                float w;
                if (c < 64)        w = Wq[kidx * DKH + c];
                else if (c < 128)  w = Wk[kidx * DKH + (c - 64)];
                else               w = Wv[kidx * CIN + (c - 128)];
                Bs[kk][c0 + j] = w;
            }
        }
        __syncthreads();
        #pragma unroll
        for (int kk = 0; kk < 16; kk++) {
            float a[4], b[4];
            #pragma unroll
            for (int i = 0; i < 4; i++) a[i] = As[ty * 4 + i][kk];
            #pragma unroll
            for (int j = 0; j < 4; j++) b[j] = Bs[kk][tx * 4 + j];
            #pragma unroll
            for (int i = 0; i < 4; i++)
                #pragma unroll
                for (int j = 0; j < 4; j++)
                    acc[i][j] = fmaf(a[i], b[j], acc[i][j]);
        }
        __syncthreads();
    }

    #pragma unroll
    for (int i = 0; i < 4; i++) {
        int row = rowBase + ty * 4 + i;
        #pragma unroll
        for (int j = 0; j < 4; j++) {
            int c = colBase + tx * 4 + j;
            float val = acc[i][j];
            if (c < 64)        q[row * DKH + c] = val;
            else if (c < 128)  k[row * DKH + (c - 64)] = val;
            else               v[row * CIN + (c - 128)] = val;
        }
    }
}

// ---------------------------------------------------------------------------
// Kernel 2: flash attention + residual.
// side=0: im1_out = softmax(q2 @ k1^T) @ v1 + im1
// side=1: im2_out = softmax(q1 @ k2^T) @ v2 + im2
// CTA: BM=32 query rows, 256 threads. Thread (rg=tid/32, lane=tid%32) owns
// rows rg*4..rg*4+3 and columns {lane + 32*j} (j=0..15) of the [32,512] acc.
// ---------------------------------------------------------------------------
__global__ __launch_bounds__(256, 2)
void attn_kernel(const float* __restrict__ im1, const float* __restrict__ im2,
                 float* __restrict__ out_all) {
    const int side = blockIdx.y;
    const float* __restrict__ Qp    = g_q[side ? 0 : 1];  // cross: out1 uses im2_q
    const float* __restrict__ Kp    = g_k[side ? 1 : 0];
    const float* __restrict__ Vp    = g_v[side ? 1 : 0];
    const float* __restrict__ resid = side ? im2 : im1;
    float* __restrict__ out = out_all + (size_t)side * NTOK * CIN;

    __shared__ float Qs[BM][68];
    __shared__ float Ks[BN][68];
    __shared__ float Vs[BN][CIN];
    __shared__ float Ss[BM][17];
    __shared__ float m_s[BM], l_s[BM], corr_s[BM];

    const int tid   = threadIdx.x;
    const int lane  = tid & 31;
    const int rg    = tid >> 5;
    const int qBase = blockIdx.x * BM;

    // Load Q tile once (32 x 64)
    #pragma unroll
    for (int t = 0; t < 2; t++) {
        int idx4 = tid + t * 256;
        int r    = idx4 >> 4;
        int c4   = idx4 & 15;
        float4 q4 = *(const float4*)(Qp + (size_t)(qBase + r) * DKH + c4 * 4);
        *(float4*)&Qs[r][c4 * 4] = q4;
    }
    if (tid < BM) { m_s[tid] = -1e30f; l_s[tid] = 0.f; }

    float acc[4][16];
    #pragma unroll
    for (int i = 0; i < 4; i++)
        #pragma unroll
        for (int j = 0; j < 16; j++) acc[i][j] = 0.f;

    // Prefetch tile 0 into registers
    float4 kreg;
    float4 vreg[8];
    {
        int kk = tid >> 4, c4 = tid & 15;
        kreg = *(const float4*)(Kp + (size_t)kk * DKH + c4 * 4);
        #pragma unroll
        for (int t = 0; t < 8; t++) {
            int idx4 = tid + t * 256;
            int vk = idx4 >> 7, vc = idx4 & 127;
            vreg[t] = *(const float4*)(Vp + (size_t)vk * CIN + vc * 4);
        }
    }

    for (int kb = 0; kb < NTOK; kb += BN) {
        // Commit staged K/V tile to smem
        {
            int kk = tid >> 4, c4 = tid & 15;
            *(float4*)&Ks[kk][c4 * 4] = kreg;
            #pragma unroll
            for (int t = 0; t < 8; t++) {
                int idx4 = tid + t * 256;
                int vk = idx4 >> 7, vc = idx4 & 127;
                *(float4*)&Vs[vk][vc * 4] = vreg[t];
            }
        }
        __syncthreads();

        // Prefetch next tile (overlaps with compute below)
        int nb = kb + BN;
        if (nb < NTOK) {
            int kk = tid >> 4, c4 = tid & 15;
            kreg = *(const float4*)(Kp + (size_t)(nb + kk) * DKH + c4 * 4);
            #pragma unroll
            for (int t = 0; t < 8; t++) {
                int idx4 = tid + t * 256;
                int vk = idx4 >> 7, vc = idx4 & 127;
                vreg[t] = *(const float4*)(Vp + (size_t)(nb + vk) * CIN + vc * 4);
            }
        }

        // Stage A: scores S[32][16] (2 dot-products of length 64 per thread)
        #pragma unroll
        for (int s = tid; s < BM * BN; s += 256) {
            int row = s >> 4;
            int key = s & 15;
            const float4* q4 = (const float4*)&Qs[row][0];
            const float4* k4 = (const float4*)&Ks[key][0];
            float d = 0.f;
            #pragma unroll
            for (int i = 0; i < 16; i++) {
                float4 qv = q4[i], kv = k4[i];
                d = fmaf(qv.x, kv.x, d);
                d = fmaf(qv.y, kv.y, d);
                d = fmaf(qv.z, kv.z, d);
                d = fmaf(qv.w, kv.w, d);
            }
            Ss[row][key] = d;
        }
        __syncthreads();

        // Stage B: per-row online softmax update (one thread per row)
        if (tid < BM) {
            float mold = m_s[tid];
            float mx   = mold;
            float sv[BN];
            #pragma unroll
            for (int kk2 = 0; kk2 < BN; kk2++) { sv[kk2] = Ss[tid][kk2]; mx = fmaxf(mx, sv[kk2]); }
            float corr = __expf(mold - mx);
            float sum  = 0.f;
            #pragma unroll
            for (int kk2 = 0; kk2 < BN; kk2++) {
                float p = __expf(sv[kk2] - mx);
                Ss[tid][kk2] = p;   // S becomes P in place
                sum += p;
            }
            l_s[tid]    = l_s[tid] * corr + sum;
            m_s[tid]    = mx;
            corr_s[tid] = corr;
        }
        __syncthreads();

        // Stage C: rescale acc, then acc += P[4,16] @ V[16, owned cols]
        {
            float c0 = corr_s[rg * 4 + 0], c1 = corr_s[rg * 4 + 1];
            float c2 = corr_s[rg * 4 + 2], c3 = corr_s[rg * 4 + 3];
            #pragma unroll
            for (int j = 0; j < 16; j++) {
                acc[0][j] *= c0; acc[1][j] *= c1; acc[2][j] *= c2; acc[3][j] *= c3;
            }
            #pragma unroll 4
            for (int kk = 0; kk < BN; kk++) {
                float p0 = Ss[rg * 4 + 0][kk];
                float p1 = Ss[rg * 4 + 1][kk];
                float p2 = Ss[rg * 4 + 2][kk];
                float p3 = Ss[rg * 4 + 3][kk];
                #pragma unroll
                for (int j = 0; j < 16; j++) {
                    float vv = Vs[kk][lane + 32 * j];   // bank = lane: conflict-free
                    acc[0][j] = fmaf(p0, vv, acc[0][j]);
                    acc[1][j] = fmaf(p1, vv, acc[1][j]);
                    acc[2][j] = fmaf(p2, vv, acc[2][j]);
                    acc[3][j] = fmaf(p3, vv, acc[3][j]);
                }
            }
        }
        __syncthreads();
    }

    // Epilogue: normalize, add residual, coalesced store
    #pragma unroll
    for (int i = 0; i < 4; i++) {
        int   row = qBase + rg * 4 + i;
        float inv = 1.0f / l_s[rg * 4 + i];
        #pragma unroll
        for (int j = 0; j < 16; j++) {
            int col = lane + 32 * j;
            out[(size_t)row * CIN + col] =
                fmaf(acc[i][j], inv, resid[(size_t)row * CIN + col]);
        }
    }
}

extern "C" void kernel_launch(void* const* d_in, const int* in_sizes, int n_in,
                              void* d_out, int out_size) {
    const float* im1 = (const float*)d_in[0];
    const float* im2 = (const float*)d_in[1];
    const float* Wq  = (const float*)d_in[2];
    const float* Wk  = (const float*)d_in[3];
    const float* Wv  = (const float*)d_in[4];
    float* out = (float*)d_out;

    dim3 pgrid(NTOK / 64, PCOLS / 64, 2);
    proj_kernel<<<pgrid, 256>>>(im1, im2, Wq, Wk, Wv);

    dim3 agrid(NTOK / BM, 2);
    attn_kernel<<<agrid, 256>>>(im1, im2, out);
}